// round 1
// baseline (speedup 1.0000x reference)
#include <cuda_runtime.h>
#include <math.h>

#define B_SZ   2
#define T_SEQ  2048
#define C_DIM  1024
#define NH     16
#define HD     64
#define M_ROWS (B_SZ * T_SEQ)   /* 4096 */
#define N_QKV  (3 * C_DIM)      /* 3072 */

// Scratch (allocation-free rule: __device__ globals)
__device__ float g_q[(size_t)B_SZ * NH * T_SEQ * HD];
__device__ float g_k[(size_t)B_SZ * NH * T_SEQ * HD];
__device__ float g_v[(size_t)B_SZ * NH * T_SEQ * HD];
__device__ float g_y[(size_t)M_ROWS * C_DIM];

// ---------------------------------------------------------------------------
// QKV GEMM: X[4096,1024] @ W[1024,3072] + b  -> scatter into g_q/g_k/g_v
// 128x128 tile, Ktile=8, 256 threads, 8x8 per thread. Q pre-scaled by 0.125.
// ---------------------------------------------------------------------------
__global__ __launch_bounds__(256) void qkv_gemm_kernel(
    const float* __restrict__ X, const float* __restrict__ W,
    const float* __restrict__ bias)
{
    const int K = C_DIM, N = N_QKV;
    __shared__ float As[8][128];
    __shared__ float Bs[8][128];

    int tid = threadIdx.x;
    int ty  = tid >> 4, tx = tid & 15;
    int row0 = blockIdx.y * 128, col0 = blockIdx.x * 128;

    int a_row = tid >> 1;            // 0..127
    int a_col = (tid & 1) << 2;      // 0 or 4
    int b_row = tid >> 5;            // 0..7
    int b_col = (tid & 31) << 2;     // 0..124

    const float* Aptr = X + (size_t)(row0 + a_row) * K + a_col;
    const float* Bptr = W + (size_t)b_row * N + col0 + b_col;

    float acc[8][8];
    #pragma unroll
    for (int i = 0; i < 8; i++)
        #pragma unroll
        for (int j = 0; j < 8; j++) acc[i][j] = 0.f;

    for (int k0 = 0; k0 < K; k0 += 8) {
        float4 av = *(const float4*)(Aptr + k0);
        float4 bv = *(const float4*)(Bptr + (size_t)k0 * N);
        As[a_col + 0][a_row] = av.x;
        As[a_col + 1][a_row] = av.y;
        As[a_col + 2][a_row] = av.z;
        As[a_col + 3][a_row] = av.w;
        *(float4*)&Bs[b_row][b_col] = bv;
        __syncthreads();

        #pragma unroll
        for (int kk = 0; kk < 8; kk++) {
            float4 a0 = *(const float4*)&As[kk][ty * 8];
            float4 a1 = *(const float4*)&As[kk][ty * 8 + 4];
            float4 b0 = *(const float4*)&Bs[kk][tx * 8];
            float4 b1 = *(const float4*)&Bs[kk][tx * 8 + 4];
            float ar[8] = {a0.x, a0.y, a0.z, a0.w, a1.x, a1.y, a1.z, a1.w};
            float br[8] = {b0.x, b0.y, b0.z, b0.w, b1.x, b1.y, b1.z, b1.w};
            #pragma unroll
            for (int i = 0; i < 8; i++)
                #pragma unroll
                for (int j = 0; j < 8; j++)
                    acc[i][j] += ar[i] * br[j];
        }
        __syncthreads();
    }

    // Epilogue: bias + scatter to [B,H,T,D] layout. Q scaled by 1/sqrt(64).
    #pragma unroll
    for (int i = 0; i < 8; i++) {
        int r  = row0 + ty * 8 + i;
        int bb = r >> 11;            // batch
        int t  = r & 2047;           // time
        #pragma unroll
        for (int j = 0; j < 8; j++) {
            int jc = col0 + tx * 8 + j;
            float val = acc[i][j] + bias[jc];
            int part = jc >> 10;     // 0=q 1=k 2=v
            int cc   = jc & 1023;
            int h    = cc >> 6;
            int d    = cc & 63;
            size_t idx = (((size_t)(bb * NH + h)) * T_SEQ + t) * HD + d;
            if (part == 0)       g_q[idx] = val * 0.125f;
            else if (part == 1)  g_k[idx] = val;
            else                 g_v[idx] = val;
        }
    }
}

// ---------------------------------------------------------------------------
// Flash attention, fp32, causal. One block = one (b,h) x one 64-row Q tile.
// 256 threads: thread (ty,tx) owns rows 4ty..4ty+3 and cols 4tx..4tx+3.
// K tile XOR-swizzled in smem to keep K-major float4 reads ~conflict-free.
// ---------------------------------------------------------------------------
__global__ __launch_bounds__(256) void attn_kernel()
{
    extern __shared__ float sm[];
    float* Qs = sm;             // 64*64
    float* Ks = sm + 4096;      // 64*64 (swizzled)
    float* Vs = sm + 8192;      // 64*64
    float* Ps = sm + 12288;     // 64*64

    int qt = blockIdx.x;        // q tile 0..31
    int bh = blockIdx.y;        // 0..31
    int b  = bh >> 4, h = bh & 15;
    const float* qbase = g_q + (size_t)bh * T_SEQ * HD + (size_t)qt * 64 * HD;
    const float* kbase = g_k + (size_t)bh * T_SEQ * HD;
    const float* vbase = g_v + (size_t)bh * T_SEQ * HD;

    int tid = threadIdx.x;
    int ty  = tid >> 4, tx = tid & 15;

    // Load Q tile (already scaled)
    #pragma unroll
    for (int p = 0; p < 4; p++) {
        int e  = p * 256 + tid;
        int m  = e >> 4;
        int d4 = (e & 15) << 2;
        *(float4*)&Qs[m * 64 + d4] = *(const float4*)(qbase + m * HD + d4);
    }

    float m_i[4], l_i[4], o[4][4];
    #pragma unroll
    for (int i = 0; i < 4; i++) {
        m_i[i] = -1e30f; l_i[i] = 0.f;
        #pragma unroll
        for (int j = 0; j < 4; j++) o[i][j] = 0.f;
    }

    for (int kt = 0; kt <= qt; kt++) {
        // Load K (swizzled) and V tiles
        #pragma unroll
        for (int p = 0; p < 4; p++) {
            int e  = p * 256 + tid;
            int n  = e >> 4;
            int d4 = (e & 15) << 2;
            int sw = d4 ^ (((n >> 2) & 7) << 3);
            size_t gofs = (size_t)(kt * 64 + n) * HD + d4;
            *(float4*)&Ks[n * 64 + sw] = *(const float4*)(kbase + gofs);
            *(float4*)&Vs[n * 64 + d4] = *(const float4*)(vbase + gofs);
        }
        __syncthreads();

        // S = Q K^T (64x64), 4x4 per thread
        float s[4][4];
        #pragma unroll
        for (int i = 0; i < 4; i++)
            #pragma unroll
            for (int j = 0; j < 4; j++) s[i][j] = 0.f;

        #pragma unroll
        for (int d4 = 0; d4 < 64; d4 += 4) {
            float4 q4[4], k4[4];
            #pragma unroll
            for (int i = 0; i < 4; i++)
                q4[i] = *(const float4*)&Qs[(ty * 4 + i) * 64 + d4];
            #pragma unroll
            for (int j = 0; j < 4; j++) {
                int n  = tx * 4 + j;
                int sw = d4 ^ (((n >> 2) & 7) << 3);
                k4[j] = *(const float4*)&Ks[n * 64 + sw];
            }
            #pragma unroll
            for (int i = 0; i < 4; i++)
                #pragma unroll
                for (int j = 0; j < 4; j++)
                    s[i][j] += q4[i].x * k4[j].x + q4[i].y * k4[j].y
                             + q4[i].z * k4[j].z + q4[i].w * k4[j].w;
        }

        // Causal mask on the diagonal tile
        if (kt == qt) {
            #pragma unroll
            for (int i = 0; i < 4; i++)
                #pragma unroll
                for (int j = 0; j < 4; j++)
                    if (tx * 4 + j > ty * 4 + i) s[i][j] = -1e30f;
        }

        // Online softmax per row (reduce over the 16 tx lanes in the half-warp)
        #pragma unroll
        for (int i = 0; i < 4; i++) {
            float tm = fmaxf(fmaxf(s[i][0], s[i][1]), fmaxf(s[i][2], s[i][3]));
            #pragma unroll
            for (int ofs = 1; ofs < 16; ofs <<= 1)
                tm = fmaxf(tm, __shfl_xor_sync(0xffffffffu, tm, ofs));
            float nm   = fmaxf(m_i[i], tm);
            float corr = __expf(m_i[i] - nm);
            m_i[i] = nm;
            float ts = 0.f;
            #pragma unroll
            for (int j = 0; j < 4; j++) {
                float p = __expf(s[i][j] - nm);
                s[i][j] = p;
                ts += p;
            }
            #pragma unroll
            for (int ofs = 1; ofs < 16; ofs <<= 1)
                ts += __shfl_xor_sync(0xffffffffu, ts, ofs);
            l_i[i] = l_i[i] * corr + ts;
            #pragma unroll
            for (int j = 0; j < 4; j++) o[i][j] *= corr;
            *(float4*)&Ps[(ty * 4 + i) * 64 + tx * 4] =
                make_float4(s[i][0], s[i][1], s[i][2], s[i][3]);
        }
        __syncthreads();

        // O += P V  (thread owns rows 4ty.., d-cols 4tx..)
        #pragma unroll
        for (int nb = 0; nb < 64; nb += 4) {
            float4 p4[4], v4[4];
            #pragma unroll
            for (int i = 0; i < 4; i++)
                p4[i] = *(const float4*)&Ps[(ty * 4 + i) * 64 + nb];
            #pragma unroll
            for (int nn = 0; nn < 4; nn++)
                v4[nn] = *(const float4*)&Vs[(nb + nn) * 64 + tx * 4];
            #pragma unroll
            for (int i = 0; i < 4; i++) {
                o[i][0] += p4[i].x * v4[0].x + p4[i].y * v4[1].x
                         + p4[i].z * v4[2].x + p4[i].w * v4[3].x;
                o[i][1] += p4[i].x * v4[0].y + p4[i].y * v4[1].y
                         + p4[i].z * v4[2].y + p4[i].w * v4[3].y;
                o[i][2] += p4[i].x * v4[0].z + p4[i].y * v4[1].z
                         + p4[i].z * v4[2].z + p4[i].w * v4[3].z;
                o[i][3] += p4[i].x * v4[0].w + p4[i].y * v4[1].w
                         + p4[i].z * v4[2].w + p4[i].w * v4[3].w;
            }
        }
        __syncthreads();
    }

    // Normalize and write to y in [B,T,C] layout (C index = h*64 + d)
    #pragma unroll
    for (int i = 0; i < 4; i++) {
        float inv = 1.0f / l_i[i];
        int t = qt * 64 + ty * 4 + i;
        float4 ov = make_float4(o[i][0] * inv, o[i][1] * inv,
                                o[i][2] * inv, o[i][3] * inv);
        *(float4*)&g_y[((size_t)(b * T_SEQ + t)) * C_DIM + h * HD + tx * 4] = ov;
    }
}

// ---------------------------------------------------------------------------
// Output projection: g_y[4096,1024] @ W_out[1024,1024] + b_out -> d_out
// ---------------------------------------------------------------------------
__global__ __launch_bounds__(256) void out_gemm_kernel(
    const float* __restrict__ W, const float* __restrict__ bias,
    float* __restrict__ out)
{
    const int K = C_DIM, N = C_DIM;
    __shared__ float As[8][128];
    __shared__ float Bs[8][128];

    int tid = threadIdx.x;
    int ty  = tid >> 4, tx = tid & 15;
    int row0 = blockIdx.y * 128, col0 = blockIdx.x * 128;

    int a_row = tid >> 1;
    int a_col = (tid & 1) << 2;
    int b_row = tid >> 5;
    int b_col = (tid & 31) << 2;

    const float* Aptr = g_y + (size_t)(row0 + a_row) * K + a_col;
    const float* Bptr = W + (size_t)b_row * N + col0 + b_col;

    float acc[8][8];
    #pragma unroll
    for (int i = 0; i < 8; i++)
        #pragma unroll
        for (int j = 0; j < 8; j++) acc[i][j] = 0.f;

    for (int k0 = 0; k0 < K; k0 += 8) {
        float4 av = *(const float4*)(Aptr + k0);
        float4 bv = *(const float4*)(Bptr + (size_t)k0 * N);
        As[a_col + 0][a_row] = av.x;
        As[a_col + 1][a_row] = av.y;
        As[a_col + 2][a_row] = av.z;
        As[a_col + 3][a_row] = av.w;
        *(float4*)&Bs[b_row][b_col] = bv;
        __syncthreads();

        #pragma unroll
        for (int kk = 0; kk < 8; kk++) {
            float4 a0 = *(const float4*)&As[kk][ty * 8];
            float4 a1 = *(const float4*)&As[kk][ty * 8 + 4];
            float4 b0 = *(const float4*)&Bs[kk][tx * 8];
            float4 b1 = *(const float4*)&Bs[kk][tx * 8 + 4];
            float ar[8] = {a0.x, a0.y, a0.z, a0.w, a1.x, a1.y, a1.z, a1.w};
            float br[8] = {b0.x, b0.y, b0.z, b0.w, b1.x, b1.y, b1.z, b1.w};
            #pragma unroll
            for (int i = 0; i < 8; i++)
                #pragma unroll
                for (int j = 0; j < 8; j++)
                    acc[i][j] += ar[i] * br[j];
        }
        __syncthreads();
    }

    #pragma unroll
    for (int i = 0; i < 8; i++) {
        int r = row0 + ty * 8 + i;
        #pragma unroll
        for (int j = 0; j < 8; j++) {
            int jc = col0 + tx * 8 + j;
            out[(size_t)r * N + jc] = acc[i][j] + bias[jc];
        }
    }
}

// ---------------------------------------------------------------------------
extern "C" void kernel_launch(void* const* d_in, const int* in_sizes, int n_in,
                              void* d_out, int out_size)
{
    (void)in_sizes; (void)n_in; (void)out_size;
    const float* x      = (const float*)d_in[0];
    // d_in[1] = causal mask (tril) -- structure hardcoded in attn_kernel
    const float* W_qkv  = (const float*)d_in[2];
    const float* b_qkv  = (const float*)d_in[3];
    const float* W_out  = (const float*)d_in[4];
    const float* b_out  = (const float*)d_in[5];
    float* out = (float*)d_out;

    qkv_gemm_kernel<<<dim3(N_QKV / 128, M_ROWS / 128), 256>>>(x, W_qkv, b_qkv);

    cudaFuncSetAttribute(attn_kernel,
                         cudaFuncAttributeMaxDynamicSharedMemorySize, 65536);
    attn_kernel<<<dim3(T_SEQ / 64, B_SZ * NH), 256, 65536>>>();

    out_gemm_kernel<<<dim3(C_DIM / 128, M_ROWS / 128), 256>>>(W_out, b_out, out);
}